// round 2
// baseline (speedup 1.0000x reference)
#include <cuda_runtime.h>

// ----------------------------------------------------------------------------
// FBP pipeline:
//   K0: tables  — ramp-filter impulse response via parallel fp64 reduction
//   K1: filter  — circular conv of the 16 BASE frames (filter ∘ lerp = lerp ∘ filter)
//   K2: backproject — 2 slices per block; lerp 16 frames -> 128 angle rows in
//       smem (guard-padded, 192 KB for both slices), index math computed once
//       per (x,y,angle) and shared by both slices.
// ----------------------------------------------------------------------------

#define MPI 3.14159265358979323846

__device__ float g_hker[128];                    // ramp filter IR * (pi/128)
__device__ float g_cos[128];
__device__ float g_sin[128];
__device__ float g_Fbase[16 * 1024 * 128];       // filtered base frames, 8 MB

// --------------------------- K0: tables (parallel) ---------------------------
// block n computes hker[n]; 128 threads each contribute one cosine term.
__global__ void k_tables() {
    __shared__ double red[128];
    int n = blockIdx.x;
    int m = threadIdx.x;
    double f = (double)(m < 64 ? m : 128 - m) / 128.0;   // |fftfreq|
    int ph = (m * n) & 127;                              // exact periodic phase
    red[m] = f * cos(2.0 * MPI * (double)ph / 128.0);
    __syncthreads();
#pragma unroll
    for (int off = 64; off > 0; off >>= 1) {
        if (m < off) red[m] += red[m + off];
        __syncthreads();
    }
    if (m == 0) g_hker[n] = (float)((red[0] / 128.0) * (MPI / 128.0));
    if (m == 1) {
        double th = MPI * (double)n / 128.0;
        g_cos[n] = (float)cos(th);
        g_sin[n] = (float)sin(th);
    }
}

// --------------------------- K1: filter -------------------------------------
// One warp per row (t,c,h): F[j] = sum_k p[k] * h[(j-k) mod 128]
__global__ __launch_bounds__(256) void k_filter(const float* __restrict__ feat) {
    __shared__ float hk[256];                    // hker duplicated: hk[i]=h[i&127]
    int tid = threadIdx.x;
    hk[tid] = g_hker[tid & 127];
    __syncthreads();

    int lane = tid & 31;
    int wid  = tid >> 5;
    int r = blockIdx.x * 8 + wid;                // row 0..16383
    const float* row = feat + (size_t)r * 128;

    float rv[4];
    rv[0] = row[lane];      rv[1] = row[lane + 32];
    rv[2] = row[lane + 64]; rv[3] = row[lane + 96];
    float a0 = 0.f, a1 = 0.f, a2 = 0.f, a3 = 0.f;

#pragma unroll
    for (int kb = 0; kb < 4; kb++) {
        float rsel = rv[kb];
#pragma unroll
        for (int kk = 0; kk < 32; kk++) {
            float x = __shfl_sync(0xffffffffu, rsel, kk);
            int base = lane + 128 - (kb * 32 + kk);   // in [1,255]
            a0 += x * hk[base];
            a1 += x * hk[base + 32];
            a2 += x * hk[base + 64];
            a3 += x * hk[base + 96];
        }
    }
    float* o = g_Fbase + (size_t)r * 128;
    o[lane] = a0; o[lane + 32] = a1; o[lane + 64] = a2; o[lane + 96] = a3;
}

// ------------------------ K2: backprojection --------------------------------
// grid = 512 blocks (2 slices each); 512 threads; dyn smem = 2 x FA[128][192]
// (32-wide zero guards on both sides kill all bounds checks).
// Index math per (x,y,angle) computed once, reused by both slices.
extern __shared__ float s_FA[];

static constexpr int FA_STRIDE = 192;            // padded row
static constexpr int FA_SLICE  = 128 * FA_STRIDE; // floats per slice (24576)

__global__ __launch_bounds__(512, 1) void k_bp(float* __restrict__ out) {
    __shared__ float sc[128], ss[128];

    int tid = threadIdx.x;
    int s0  = blockIdx.x * 2;                    // slices s0, s0+1

    if (tid < 128) { sc[tid] = g_cos[tid]; ss[tid] = g_sin[tid]; }

    // zero guard bands: 2 slices x 128 angles x (32 left + 32 right)
    for (int g = tid; g < 2 * 8192; g += 512) {
        int sl = g >> 13;
        int gg = g & 8191;
        int a = gg >> 6;
        int q = gg & 63;
        int col = (q < 32) ? q : (128 + q);      // [0,32) and [160,192)
        s_FA[sl * FA_SLICE + a * FA_STRIDE + col] = 0.f;
    }

    // interior: lerp 16 filtered base frames -> 128 angle rows, both slices
    for (int e = tid; e < 2 * 16384; e += 512) {
        int sl = e >> 14;
        int ee = e & 16383;
        int a = ee >> 7, w = ee & 127;
        int t0 = a >> 3;
        float v = (float)(a & 7) * 0.125f;
        int s = s0 + sl;
        float f0 = g_Fbase[(size_t)(t0 * 1024 + s) * 128 + w];
        float f1 = g_Fbase[(size_t)(((t0 + 1) & 15) * 1024 + s) * 128 + w];
        s_FA[sl * FA_SLICE + a * FA_STRIDE + 32 + w] = fmaf(v, f1 - f0, f0);
    }
    __syncthreads();

    // each thread: one x, 32 consecutive y, BOTH slices
    int x  = tid >> 2;                           // 0..127
    int y0 = (tid & 3) << 5;                     // 0,32,64,96
    float xa = (float)x  - 63.5f;
    float yb = (float)y0 - 63.5f;

    float acc0[32], acc1[32];
#pragma unroll
    for (int i = 0; i < 32; i++) { acc0[i] = 0.f; acc1[i] = 0.f; }

    for (int a = 0; a < 128; a++) {
        float c  = sc[a];
        float sn = ss[a];
        // +63.5 detector center, +32 guard offset
        float u0 = fmaf(xa, c, fmaf(yb, sn, 95.5f));
        const float* r0 = s_FA + a * FA_STRIDE;
        const float* r1 = r0 + FA_SLICE;
#pragma unroll
        for (int yy = 0; yy < 32; yy++) {
            float u  = fmaf((float)yy, sn, u0);
            float t  = u + 8388607.5f;                 // 2^23 - 0.5: RN -> floor
            int   it = __float_as_int(t) - 0x4B000000; // floor(u) as int
            float fl = t - 8388608.0f;                 // floor(u) as float (exact)
            float fr = u - fl;                         // frac (Sterbenz exact)
            float om = 1.0f - fr;
            float g0a = r0[it], g1a = r0[it + 1];
            float g0b = r1[it], g1b = r1[it + 1];
            acc0[yy] = fmaf(g0a, om, fmaf(g1a, fr, acc0[yy]));
            acc1[yy] = fmaf(g0b, om, fmaf(g1b, fr, acc1[yy]));
        }
    }

    float* op0 = out + (size_t)s0 * 16384 + x * 128 + y0;
    float* op1 = op0 + 16384;
#pragma unroll
    for (int yy = 0; yy < 32; yy += 4) {
        *(float4*)(op0 + yy) = make_float4(acc0[yy], acc0[yy+1], acc0[yy+2], acc0[yy+3]);
        *(float4*)(op1 + yy) = make_float4(acc1[yy], acc1[yy+1], acc1[yy+2], acc1[yy+3]);
    }
}

// ----------------------------------------------------------------------------
extern "C" void kernel_launch(void* const* d_in, const int* in_sizes, int n_in,
                              void* d_out, int out_size) {
    (void)in_sizes; (void)n_in; (void)out_size;
    const float* feat = (const float*)d_in[0];
    float* out = (float*)d_out;

    static int cfg_done = 0;
    int smem_bytes = 2 * FA_SLICE * (int)sizeof(float);   // 196608
    cudaFuncSetAttribute(k_bp, cudaFuncAttributeMaxDynamicSharedMemorySize,
                         smem_bytes);
    (void)cfg_done;

    k_tables<<<128, 128>>>();
    k_filter<<<2048, 256>>>(feat);
    k_bp<<<512, 512, smem_bytes>>>(out);
}